// round 1
// baseline (speedup 1.0000x reference)
#include <cuda_runtime.h>
#include <math.h>

// LIF cell scan: v = v*sigmoid(decay)*(1-z) + x_t ; z = (v > 0.5)
// x: [B,T,H] f32, decay: [H] f32, v0: [B,H] f32, z0: [B,H] f32
// out: [B,T,H] f32 (spikes)
//
// Parallelization: one thread per (b,h) sequence; sequential loop over T.
// Adjacent threads = adjacent h -> every x load / out store is a fully
// coalesced 128B warp transaction. t-loop unrolled x8 so 8 independent
// streaming loads are in flight ahead of the (serial, cheap) recurrence.

#define LIF_B 512
#define LIF_T 512
#define LIF_H 256
#define THRESH 0.5f
#define UNROLL 8

__global__ __launch_bounds__(256) void lif_scan_kernel(
    const float* __restrict__ x,
    const float* __restrict__ decay,
    const float* __restrict__ v0,
    const float* __restrict__ z0,
    float* __restrict__ out)
{
    const int idx = blockIdx.x * blockDim.x + threadIdx.x;  // 0 .. B*H-1
    const int h = idx & (LIF_H - 1);
    const int b = idx >> 8;   // H = 256 = 2^8

    // sigmoid(decay[h]) — accurate expf; computed once, amortized over T.
    const float dparam = decay[h];
    const float d = 1.0f / (1.0f + expf(-dparam));

    float v = v0[idx];
    float z = z0[idx];

    const float* xp = x   + (long)b * (LIF_T * LIF_H) + h;
    float*       op = out + (long)b * (LIF_T * LIF_H) + h;

    for (int t = 0; t < LIF_T; t += UNROLL) {
        // Batch 8 independent streaming loads (MLP for DRAM latency hiding).
        float xt[UNROLL];
#pragma unroll
        for (int u = 0; u < UNROLL; u++) {
            xt[u] = __ldcs(xp + (t + u) * LIF_H);
        }
        // Serial recurrence (cheap: 2 FMA-class ops + select per step).
#pragma unroll
        for (int u = 0; u < UNROLL; u++) {
            v = v * d * (1.0f - z) + xt[u];
            z = (v > THRESH) ? 1.0f : 0.0f;
            __stcs(op + (t + u) * LIF_H, z);
        }
    }
}

extern "C" void kernel_launch(void* const* d_in, const int* in_sizes, int n_in,
                              void* d_out, int out_size) {
    const float* x     = (const float*)d_in[0];  // [B,T,H]
    const float* decay = (const float*)d_in[1];  // [H]
    const float* v0    = (const float*)d_in[2];  // [B,H]
    const float* z0    = (const float*)d_in[3];  // [B,H]
    float* out = (float*)d_out;                  // [B,T,H]

    const int n_seq = LIF_B * LIF_H;             // 131072 threads
    const int threads = 256;
    const int blocks = n_seq / threads;          // 512 blocks

    lif_scan_kernel<<<blocks, threads>>>(x, decay, v0, z0, out);
}